// round 1
// baseline (speedup 1.0000x reference)
#include <cuda_runtime.h>

#define NMAX  100000
#define NF    512
#define NH    8
#define NC    16

// ---------------- scratch (no allocations allowed) ----------------
__device__ float g_s1[NMAX * NH];    // x @ W1 (pre-spmm)
__device__ float g_xr[NMAX * NH];    // affine(relu(bi-interaction))
__device__ float g_agg1[NMAX * NH];  // spmm(adj, s1)
__device__ float g_s2[NMAX * NC];    // h @ W2

typedef unsigned long long u64;

// ---------------- f32x2 helpers (FFMA2 = full-rate fp32 on sm_103a) ---
#define PACK2(out, lo, hi) \
    asm("mov.b64 %0, {%1, %2};" : "=l"(out) : "f"(lo), "f"(hi))
#define UNPACK2(lo, hi, in) \
    asm("mov.b64 {%0, %1}, %2;" : "=f"(lo), "=f"(hi) : "l"(in))
#define MUL2(out, a, b) \
    asm("mul.rn.f32x2 %0, %1, %2;" : "=l"(out) : "l"(a), "l"(b))
#define FMA2(acc, a, b) \
    asm("fma.rn.f32x2 %0, %1, %2, %0;" : "+l"(acc) : "l"(a), "l"(b))

__device__ __forceinline__ void redv4(float* p, float a, float b, float c, float d) {
    asm volatile("red.global.add.v4.f32 [%0], {%1,%2,%3,%4};"
                 :: "l"(p), "f"(a), "f"(b), "f"(c), "f"(d) : "memory");
}

// ---------------- kernel 0: zero the atomic accumulators --------------
__global__ void k_zero(float* __restrict__ out, int n) {
    int i = blockIdx.x * blockDim.x + threadIdx.x;
    int n1 = n * NH / 4;   // float4 count in g_agg1
    int n2 = n * NC / 4;   // float4 count in out
    float4 z = make_float4(0.f, 0.f, 0.f, 0.f);
    if (i < n1) ((float4*)g_agg1)[i] = z;
    if (i < n2) ((float4*)out)[i] = z;
}

// ---------------- kernel 1: fused x@W1 / x@V / x^2@V^2 ----------------
// One thread = one node, all 24 outputs. Weights live in SMEM and every
// lane in a warp reads the SAME weight address -> broadcast (conflict-free).
// k-pairs packed into f32x2 accumulators.
#define KCHUNK 64
#define XPITCH 68   // 64 + 4 pad: keeps float4 align (272B) and spreads banks

__global__ void __launch_bounds__(256) k_gemmA(
    const float* __restrict__ x, const float* __restrict__ W1,
    const float* __restrict__ V, const float* __restrict__ gamma,
    const float* __restrict__ beta, int n)
{
    extern __shared__ float sm[];
    float* wT = sm;                 // [24][512]  (48 KB)
    float* xs = sm + 24 * NF;       // [256][68]  (68 KB)
    const int tid = threadIdx.x;
    const int nb  = blockIdx.x * 256;

    // stage combined weights, transposed to [out][k]
    for (int i = tid; i < NF * NH; i += 256) {
        int k = i >> 3, h = i & 7;
        float a = W1[i];
        float b = V[i];
        wT[h * NF + k]        = a;
        wT[(8 + h) * NF + k]  = b;
        wT[(16 + h) * NF + k] = b * b;
    }

    u64 a1[8], av[8], a2[8];
#pragma unroll
    for (int h = 0; h < 8; h++) { a1[h] = 0ull; av[h] = 0ull; a2[h] = 0ull; }

    for (int kc = 0; kc < NF; kc += KCHUNK) {
        __syncthreads();
        // stage x chunk [256 nodes][64 k] coalesced
        for (int idx = tid; idx < 256 * 16; idx += 256) {
            int r = idx >> 4, c4 = idx & 15;
            int gn = nb + r;
            float4 val = make_float4(0.f, 0.f, 0.f, 0.f);
            if (gn < n) val = *(const float4*)(x + (size_t)gn * NF + kc + c4 * 4);
            *(float4*)(xs + r * XPITCH + c4 * 4) = val;
        }
        __syncthreads();

#pragma unroll 2
        for (int kk = 0; kk < KCHUNK; kk += 4) {
            float4 xf = *(const float4*)(xs + tid * XPITCH + kk);
            u64 xA, xB, xA2, xB2;
            PACK2(xA, xf.x, xf.y);
            PACK2(xB, xf.z, xf.w);
            MUL2(xA2, xA, xA);
            MUL2(xB2, xB, xB);
            const float* wb = wT + kc + kk;
#pragma unroll
            for (int h = 0; h < 8; h++) {
                float4 w1f = *(const float4*)(wb + h * NF);          // broadcast
                float4 vf  = *(const float4*)(wb + (8 + h) * NF);    // broadcast
                float4 v2f = *(const float4*)(wb + (16 + h) * NF);   // broadcast
                u64 t;
                PACK2(t, w1f.x, w1f.y); FMA2(a1[h], xA,  t);
                PACK2(t, w1f.z, w1f.w); FMA2(a1[h], xB,  t);
                PACK2(t, vf.x,  vf.y);  FMA2(av[h], xA,  t);
                PACK2(t, vf.z,  vf.w);  FMA2(av[h], xB,  t);
                PACK2(t, v2f.x, v2f.y); FMA2(a2[h], xA2, t);
                PACK2(t, v2f.z, v2f.w); FMA2(a2[h], xB2, t);
            }
        }
    }

    int node = nb + tid;
    if (node < n) {
#pragma unroll
        for (int h = 0; h < 8; h++) {
            float l0, l1;
            UNPACK2(l0, l1, a1[h]); float s1v  = l0 + l1;
            UNPACK2(l0, l1, av[h]); float xv   = l0 + l1;
            UNPACK2(l0, l1, a2[h]); float x2v2 = l0 + l1;
            float r = 0.5f * (xv * xv - x2v2);
            r = r > 0.f ? r : 0.f;
            g_s1[(size_t)node * NH + h] = s1v;
            g_xr[(size_t)node * NH + h] = gamma[h] * r + beta[h];
        }
    }
}

// ---------------- kernel 2: spmm1 (COO, vector atomics) ---------------
__global__ void k_spmm1(const int* __restrict__ rows, const int* __restrict__ cols,
                        const float* __restrict__ vals, int e)
{
    int i = blockIdx.x * blockDim.x + threadIdx.x;
    if (i >= e) return;
    int   r = rows[i];
    int   c = cols[i];
    float v = vals[i];
    const float4* s = (const float4*)(g_s1 + (size_t)c * NH);
    float4 p0 = s[0], p1 = s[1];
    float* dst = g_agg1 + (size_t)r * NH;
    redv4(dst,     v * p0.x, v * p0.y, v * p0.z, v * p0.w);
    redv4(dst + 4, v * p1.x, v * p1.y, v * p1.z, v * p1.w);
}

// ---------------- kernel 3: relu+bias, merge branches, h@W2 -----------
__global__ void k_mid(const float* __restrict__ b1, const float* __restrict__ W2, int n)
{
    __shared__ float w2s[NH * NC];
    __shared__ float b1s[NH];
    int tid = threadIdx.x;
    if (tid < NH * NC) w2s[tid] = W2[tid];
    if (tid < NH)      b1s[tid] = b1[tid];
    __syncthreads();
    int node = blockIdx.x * blockDim.x + tid;
    if (node >= n) return;
    float h[NH];
#pragma unroll
    for (int j = 0; j < NH; j++) {
        float l = g_agg1[(size_t)node * NH + j] + b1s[j];
        l = l > 0.f ? l : 0.f;
        h[j] = 0.5f * (l + g_xr[(size_t)node * NH + j]);
    }
#pragma unroll
    for (int c = 0; c < NC; c++) {
        float acc = 0.f;
#pragma unroll
        for (int j = 0; j < NH; j++) acc = fmaf(h[j], w2s[j * NC + c], acc);
        g_s2[(size_t)node * NC + c] = acc;
    }
}

// ---------------- kernel 4: spmm2 into d_out --------------------------
__global__ void k_spmm2(const int* __restrict__ rows, const int* __restrict__ cols,
                        const float* __restrict__ vals, float* __restrict__ out, int e)
{
    int i = blockIdx.x * blockDim.x + threadIdx.x;
    if (i >= e) return;
    int   r = rows[i];
    int   c = cols[i];
    float v = vals[i];
    const float4* s = (const float4*)(g_s2 + (size_t)c * NC);
    float* dst = out + (size_t)r * NC;
#pragma unroll
    for (int q = 0; q < 4; q++) {
        float4 p = s[q];
        redv4(dst + q * 4, v * p.x, v * p.y, v * p.z, v * p.w);
    }
}

// ---------------- kernel 5: + b2, log_softmax (in place) --------------
__global__ void k_lsm(float* __restrict__ out, const float* __restrict__ b2, int n)
{
    __shared__ float b2s[NC];
    if (threadIdx.x < NC) b2s[threadIdx.x] = b2[threadIdx.x];
    __syncthreads();
    int node = blockIdx.x * blockDim.x + threadIdx.x;
    if (node >= n) return;
    float v[NC];
    float4* p = (float4*)(out + (size_t)node * NC);
#pragma unroll
    for (int q = 0; q < 4; q++) {
        float4 t = p[q];
        v[q * 4 + 0] = t.x + b2s[q * 4 + 0];
        v[q * 4 + 1] = t.y + b2s[q * 4 + 1];
        v[q * 4 + 2] = t.z + b2s[q * 4 + 2];
        v[q * 4 + 3] = t.w + b2s[q * 4 + 3];
    }
    float m = v[0];
#pragma unroll
    for (int c = 1; c < NC; c++) m = fmaxf(m, v[c]);
    float s = 0.f;
#pragma unroll
    for (int c = 0; c < NC; c++) s += expf(v[c] - m);
    float lse = m + logf(s);
#pragma unroll
    for (int q = 0; q < 4; q++) {
        float4 t;
        t.x = v[q * 4 + 0] - lse;
        t.y = v[q * 4 + 1] - lse;
        t.z = v[q * 4 + 2] - lse;
        t.w = v[q * 4 + 3] - lse;
        p[q] = t;
    }
}

// ---------------- launcher -------------------------------------------
extern "C" void kernel_launch(void* const* d_in, const int* in_sizes, int n_in,
                              void* d_out, int out_size)
{
    const float* x     = (const float*)d_in[0];
    const int*   rows  = (const int*)d_in[1];
    const int*   cols  = (const int*)d_in[2];
    const float* vals  = (const float*)d_in[3];
    const float* W1    = (const float*)d_in[4];
    const float* b1    = (const float*)d_in[5];
    const float* W2    = (const float*)d_in[6];
    const float* b2    = (const float*)d_in[7];
    const float* V     = (const float*)d_in[8];
    const float* gamma = (const float*)d_in[9];
    const float* beta  = (const float*)d_in[10];
    float* out = (float*)d_out;

    int n = in_sizes[0] / NF;   // 100000
    int e = in_sizes[1];        // 3200000

    int smem = (24 * NF + 256 * XPITCH) * (int)sizeof(float);
    cudaFuncSetAttribute(k_gemmA, cudaFuncAttributeMaxDynamicSharedMemorySize, smem);

    {   // zero g_agg1 + d_out
        int n2 = n * NC / 4;
        int blocks = (n2 + 255) / 256;
        k_zero<<<blocks, 256>>>(out, n);
    }
    {   // fused input GEMM
        int blocks = (n + 255) / 256;
        k_gemmA<<<blocks, 256, smem>>>(x, W1, V, gamma, beta, n);
    }
    {   // spmm1
        int blocks = (e + 255) / 256;
        k_spmm1<<<blocks, 256>>>(rows, cols, vals, e);
    }
    {   // mid
        int blocks = (n + 255) / 256;
        k_mid<<<blocks, 256>>>(b1, W2, n);
    }
    {   // spmm2
        int blocks = (e + 255) / 256;
        k_spmm2<<<blocks, 256>>>(rows, cols, vals, out, e);
    }
    {   // log_softmax
        int blocks = (n + 255) / 256;
        k_lsm<<<blocks, 256>>>(out, b2, n);
    }
}